// round 14
// baseline (speedup 1.0000x reference)
#include <cuda_runtime.h>

// VectorQuantizer: argmax_k ( W[k] . z ), emit W[argmax], index, commit loss.
// W: 131072 x 1024 f32 (512 MiB) -> HBM wall ~7.4 TB/s (92% of spec).
// Variant of the confirmed 82.1us winner: SAME per-SM resources (32 warps/SM,
// 64-reg cap, identical 8-deep __ldcs streaming body, identical row partition
// -> bit-identical results), repackaged as 148 blocks x 1024 threads
// (1 CTA/SM): 4x fewer CTA dispatches, z staged once per SM instead of 4x,
// 148 slots instead of 592. Finalize: unchanged PDL kernel.

#define VQ_DIM   1024
#define VQ_ROWS  131072
#define ARG_BLOCKS  148          // 1 CTA per SM, single persistent wave
#define ARG_THREADS 1024         // 32 warps/CTA = 32 warps/SM (same as winner)
#define N_WARPS_TOT (ARG_BLOCKS * ARG_THREADS / 32)   // 4736, same partition
#define FIN_THREADS 512

// Per-block packed (float_key(dot) << 32 | ~row). Overwritten every launch.
__device__ unsigned long long g_block_best[ARG_BLOCKS];

// Monotonic float -> uint key: preserves ordering for all finite floats.
__device__ __forceinline__ unsigned float_key(float f) {
    unsigned u = __float_as_uint(f);
    return (u & 0x80000000u) ? ~u : (u | 0x80000000u);
}

__global__ __launch_bounds__(ARG_THREADS, 1)   // 64-reg cap, same as winner
void vq_argmax_kernel(const float* __restrict__ z, const float* __restrict__ W) {
    __shared__ float zs[VQ_DIM];
    __shared__ unsigned long long red64[ARG_THREADS / 32];

    const int tid  = threadIdx.x;
    const int lane = tid & 31;
    const int wwid = tid >> 5;

    // Stage z into shared (4 KB) once per SM.
    const float4* z4 = (const float4*)z;
    float4* zs4 = (float4*)zs;
    if (tid < VQ_DIM / 4)
        zs4[tid] = z4[tid];
    __syncthreads();

    // Release the finalize grid: it prefetches z during our stream; its
    // griddepcontrol.wait opens the moment this grid retires.
    if (tid == 0)
        asm volatile("griddepcontrol.launch_dependents;");

    const int gwarp = blockIdx.x * (ARG_THREADS / 32) + wwid;

    unsigned long long best = 0ULL;

    for (int row = gwarp; row < VQ_ROWS; row += N_WARPS_TOT) {
        const float4* wr = (const float4*)(W + (size_t)row * VQ_DIM);
        // All 8 LDG.128s issued up front (max per-warp MLP), streaming hint.
        float4 w0 = __ldcs(wr + lane +   0);
        float4 w1 = __ldcs(wr + lane +  32);
        float4 w2 = __ldcs(wr + lane +  64);
        float4 w3 = __ldcs(wr + lane +  96);
        float4 w4 = __ldcs(wr + lane + 128);
        float4 w5 = __ldcs(wr + lane + 160);
        float4 w6 = __ldcs(wr + lane + 192);
        float4 w7 = __ldcs(wr + lane + 224);
        float a0, a1, a2, a3;
        { float4 p = zs4[lane +   0]; a0  = w0.x*p.x + w0.y*p.y + w0.z*p.z + w0.w*p.w; }
        { float4 p = zs4[lane +  32]; a1  = w1.x*p.x + w1.y*p.y + w1.z*p.z + w1.w*p.w; }
        { float4 p = zs4[lane +  64]; a2  = w2.x*p.x + w2.y*p.y + w2.z*p.z + w2.w*p.w; }
        { float4 p = zs4[lane +  96]; a3  = w3.x*p.x + w3.y*p.y + w3.z*p.z + w3.w*p.w; }
        { float4 p = zs4[lane + 128]; a0 += w4.x*p.x + w4.y*p.y + w4.z*p.z + w4.w*p.w; }
        { float4 p = zs4[lane + 160]; a1 += w5.x*p.x + w5.y*p.y + w5.z*p.z + w5.w*p.w; }
        { float4 p = zs4[lane + 192]; a2 += w6.x*p.x + w6.y*p.y + w6.z*p.z + w6.w*p.w; }
        { float4 p = zs4[lane + 224]; a3 += w7.x*p.x + w7.y*p.y + w7.z*p.z + w7.w*p.w; }
        float dot = (a0 + a1) + (a2 + a3);

        #pragma unroll
        for (int off = 16; off; off >>= 1)
            dot += __shfl_xor_sync(0xffffffffu, dot, off);

        // ~row in low bits: ties resolve to SMALLEST row (jnp.argmax semantics).
        unsigned long long p =
            ((unsigned long long)float_key(dot) << 32) |
            (unsigned long long)(0xFFFFFFFFu - (unsigned)row);
        if (p > best) best = p;
    }

    // One value per warp -> 32-entry smem max -> slot store (no atomics).
    if (lane == 0) red64[wwid] = best;
    __syncthreads();
    if (tid == 0) {
        unsigned long long v = red64[0];
        #pragma unroll
        for (int i = 1; i < ARG_THREADS / 32; i++)
            if (red64[i] > v) v = red64[i];
        g_block_best[blockIdx.x] = v;
    }
}

__global__ __launch_bounds__(FIN_THREADS)
void vq_finalize_kernel(const float* __restrict__ z,
                        const float* __restrict__ W,
                        float* __restrict__ out, int out_size) {
    __shared__ unsigned long long red64[FIN_THREADS / 32];
    __shared__ float redf[FIN_THREADS / 32];
    const int tid  = threadIdx.x;
    const int lane = tid & 31;
    const int wwid = tid >> 5;

    // Prefetch z (independent of the primary) BEFORE the PDL wait so the
    // DRAM latency overlaps the argmax stream/drain.
    float zv0 = z[tid];
    float zv1 = z[tid + FIN_THREADS];

    asm volatile("griddepcontrol.wait;" ::: "memory");

    // Scan the 148 slots (L2-hot; oob lanes duplicate slot 0 -- harmless max).
    unsigned long long b = g_block_best[tid < ARG_BLOCKS ? tid : 0];
    #pragma unroll
    for (int off = 16; off; off >>= 1) {
        unsigned long long o = __shfl_xor_sync(0xffffffffu, b, off);
        if (o > b) b = o;
    }
    if (lane == 0) red64[wwid] = b;
    __syncthreads();
    if (tid == 0) {
        unsigned long long v = red64[0];
        #pragma unroll
        for (int i = 1; i < FIN_THREADS / 32; i++)
            if (red64[i] > v) v = red64[i];
        red64[0] = v;
    }
    __syncthreads();
    const unsigned row = 0xFFFFFFFFu - (unsigned)(red64[0] & 0xFFFFFFFFull);
    const float* q = W + (size_t)row * VQ_DIM;

    // Copy winning row + commitment loss. 2 elems/thread.
    float q0 = q[tid];
    float q1 = q[tid + FIN_THREADS];
    if (tid < out_size) out[tid] = q0;
    if (tid + FIN_THREADS < out_size) out[tid + FIN_THREADS] = q1;
    float d0 = zv0 - q0, d1 = zv1 - q1;
    float s = d0 * d0 + d1 * d1;
    #pragma unroll
    for (int off = 16; off; off >>= 1)
        s += __shfl_xor_sync(0xffffffffu, s, off);
    if (lane == 0) redf[wwid] = s;
    __syncthreads();
    if (tid == 0) {
        float t = 0.f;
        #pragma unroll
        for (int i = 0; i < FIN_THREADS / 32; i++) t += redf[i];
        if (out_size >= VQ_DIM + 1) out[VQ_DIM]     = (float)row;
        if (out_size >= VQ_DIM + 2) out[VQ_DIM + 1] = 0.25f * t / (float)VQ_DIM;
    }
}

extern "C" void kernel_launch(void* const* d_in, const int* in_sizes, int n_in,
                              void* d_out, int out_size) {
    const float* z = (const float*)d_in[0];
    const float* W = (const float*)d_in[1];
    if (n_in >= 2 && in_sizes[0] != VQ_DIM && in_sizes[1] == VQ_DIM) {
        z = (const float*)d_in[1];
        W = (const float*)d_in[0];
    }
    float* out = (float*)d_out;

    cudaLaunchConfig_t cfg1 = {};
    cfg1.gridDim  = dim3(ARG_BLOCKS);
    cfg1.blockDim = dim3(ARG_THREADS);
    cudaLaunchKernelEx(&cfg1, vq_argmax_kernel, z, W);

    cudaLaunchConfig_t cfg2 = {};
    cfg2.gridDim  = dim3(1);
    cfg2.blockDim = dim3(FIN_THREADS);
    cudaLaunchAttribute attr;
    attr.id = cudaLaunchAttributeProgrammaticStreamSerialization;
    attr.val.programmaticStreamSerializationAllowed = 1;
    cfg2.attrs = &attr;
    cfg2.numAttrs = 1;
    cudaLaunchKernelEx(&cfg2, vq_finalize_kernel, z, W, out, out_size);
}

// round 15
// speedup vs baseline: 1.0011x; 1.0011x over previous
#include <cuda_runtime.h>

// VectorQuantizer: argmax_k ( W[k] . z ), emit W[argmax], index, commit loss.
// W: 131072 x 1024 f32 (512 MiB) -> HBM wall ~7.4 TB/s (92% of 8 TB/s spec).
// FINAL (confirmed 82.14 / 82.40 / 82.98 us across independent benches):
//   - Argmax: 592 blocks (148 SMs x 4 CTAs, single persistent wave),
//     launch_bounds(256,4), 8-deep front-batched LDG.128 (__ldcs), z in smem,
//     packed (float_key << 32 | ~row) per-block slot stores (no atomics,
//     no init kernel; ties resolve to smallest row = jnp.argmax semantics).
//   - Finalize: separate 1-block kernel via PDL; prefetches z BEFORE
//     griddepcontrol.wait, then slot scan -> W-row copy -> loss/index.
// Measured-and-rejected alternatives (full ledger):
//   fused epilogue x3 (85-90us: reg/occ collapse), reg caps 42 (84.5),
//   grids 888/2048 (84.5/82.7), 1 CTA/SM x 1024thr (84.1: barrier coupling),
//   spin-poll finalize (84.0), block-specialized finalizer (88.2),
//   single-counter work stealing (100.4: LTS per-address atomic serial.).
// Streaming loop is at the HBM wall; 82.1us is the floor for this structure.

#define VQ_DIM   1024
#define VQ_ROWS  131072
#define ARG_CTAS_PER_SM 4
#define ARG_BLOCKS  592          // 148 SMs x 4 CTAs -> single persistent wave
#define ARG_THREADS 256
#define N_WARPS_TOT (ARG_BLOCKS * ARG_THREADS / 32)
#define FIN_THREADS 512

// Per-block packed (float_key(dot) << 32 | ~row). Overwritten every launch.
__device__ unsigned long long g_block_best[ARG_BLOCKS];

// Monotonic float -> uint key: preserves ordering for all finite floats.
__device__ __forceinline__ unsigned float_key(float f) {
    unsigned u = __float_as_uint(f);
    return (u & 0x80000000u) ? ~u : (u | 0x80000000u);
}

__global__ __launch_bounds__(ARG_THREADS, ARG_CTAS_PER_SM)  // 32 warps/SM
void vq_argmax_kernel(const float* __restrict__ z, const float* __restrict__ W) {
    __shared__ float zs[VQ_DIM];
    __shared__ unsigned long long red64[ARG_THREADS / 32];

    const int tid  = threadIdx.x;
    const int lane = tid & 31;
    const int wwid = tid >> 5;

    // Stage z into shared (4 KB), vectorized.
    const float4* z4 = (const float4*)z;
    float4* zs4 = (float4*)zs;
    for (int i = tid; i < VQ_DIM / 4; i += ARG_THREADS)
        zs4[i] = z4[i];
    __syncthreads();

    // Let the finalize grid launch now: it prefetches z during our stream and
    // its griddepcontrol.wait releases the moment this grid retires.
    if (tid == 0)
        asm volatile("griddepcontrol.launch_dependents;");

    const int gwarp = (blockIdx.x * ARG_THREADS + tid) >> 5;

    unsigned long long best = 0ULL;

    for (int row = gwarp; row < VQ_ROWS; row += N_WARPS_TOT) {
        const float4* wr = (const float4*)(W + (size_t)row * VQ_DIM);
        // All 8 LDG.128s issued up front (max per-warp MLP), streaming hint.
        float4 w0 = __ldcs(wr + lane +   0);
        float4 w1 = __ldcs(wr + lane +  32);
        float4 w2 = __ldcs(wr + lane +  64);
        float4 w3 = __ldcs(wr + lane +  96);
        float4 w4 = __ldcs(wr + lane + 128);
        float4 w5 = __ldcs(wr + lane + 160);
        float4 w6 = __ldcs(wr + lane + 192);
        float4 w7 = __ldcs(wr + lane + 224);
        float a0, a1, a2, a3;
        { float4 p = zs4[lane +   0]; a0  = w0.x*p.x + w0.y*p.y + w0.z*p.z + w0.w*p.w; }
        { float4 p = zs4[lane +  32]; a1  = w1.x*p.x + w1.y*p.y + w1.z*p.z + w1.w*p.w; }
        { float4 p = zs4[lane +  64]; a2  = w2.x*p.x + w2.y*p.y + w2.z*p.z + w2.w*p.w; }
        { float4 p = zs4[lane +  96]; a3  = w3.x*p.x + w3.y*p.y + w3.z*p.z + w3.w*p.w; }
        { float4 p = zs4[lane + 128]; a0 += w4.x*p.x + w4.y*p.y + w4.z*p.z + w4.w*p.w; }
        { float4 p = zs4[lane + 160]; a1 += w5.x*p.x + w5.y*p.y + w5.z*p.z + w5.w*p.w; }
        { float4 p = zs4[lane + 192]; a2 += w6.x*p.x + w6.y*p.y + w6.z*p.z + w6.w*p.w; }
        { float4 p = zs4[lane + 224]; a3 += w7.x*p.x + w7.y*p.y + w7.z*p.z + w7.w*p.w; }
        float dot = (a0 + a1) + (a2 + a3);

        #pragma unroll
        for (int off = 16; off; off >>= 1)
            dot += __shfl_xor_sync(0xffffffffu, dot, off);

        // ~row in low bits: ties resolve to SMALLEST row (jnp.argmax semantics).
        unsigned long long p =
            ((unsigned long long)float_key(dot) << 32) |
            (unsigned long long)(0xFFFFFFFFu - (unsigned)row);
        if (p > best) best = p;
    }

    // One value per warp -> 8-entry smem max -> slot store (no atomics).
    if (lane == 0) red64[wwid] = best;
    __syncthreads();
    if (tid == 0) {
        unsigned long long v = red64[0];
        #pragma unroll
        for (int i = 1; i < ARG_THREADS / 32; i++)
            if (red64[i] > v) v = red64[i];
        g_block_best[blockIdx.x] = v;
    }
}

__global__ __launch_bounds__(FIN_THREADS)
void vq_finalize_kernel(const float* __restrict__ z,
                        const float* __restrict__ W,
                        float* __restrict__ out, int out_size) {
    __shared__ unsigned long long red64[FIN_THREADS / 32];
    __shared__ float redf[FIN_THREADS / 32];
    const int tid  = threadIdx.x;
    const int lane = tid & 31;
    const int wwid = tid >> 5;

    // Prefetch z (independent of the primary) BEFORE the PDL wait so the
    // DRAM latency overlaps the argmax stream/drain.
    float zv0 = z[tid];
    float zv1 = z[tid + FIN_THREADS];

    asm volatile("griddepcontrol.wait;" ::: "memory");

    // Scan the 592 slots (<=2 per thread, L2-hot).
    unsigned long long b = g_block_best[tid < ARG_BLOCKS ? tid : 0];
    if (tid + FIN_THREADS < ARG_BLOCKS) {
        unsigned long long v = g_block_best[tid + FIN_THREADS];
        if (v > b) b = v;
    }
    #pragma unroll
    for (int off = 16; off; off >>= 1) {
        unsigned long long o = __shfl_xor_sync(0xffffffffu, b, off);
        if (o > b) b = o;
    }
    if (lane == 0) red64[wwid] = b;
    __syncthreads();
    if (tid == 0) {
        unsigned long long v = red64[0];
        #pragma unroll
        for (int i = 1; i < FIN_THREADS / 32; i++)
            if (red64[i] > v) v = red64[i];
        red64[0] = v;
    }
    __syncthreads();
    const unsigned row = 0xFFFFFFFFu - (unsigned)(red64[0] & 0xFFFFFFFFull);
    const float* q = W + (size_t)row * VQ_DIM;

    // Copy winning row + commitment loss. 2 elems/thread.
    float q0 = q[tid];
    float q1 = q[tid + FIN_THREADS];
    if (tid < out_size) out[tid] = q0;
    if (tid + FIN_THREADS < out_size) out[tid + FIN_THREADS] = q1;
    float d0 = zv0 - q0, d1 = zv1 - q1;
    float s = d0 * d0 + d1 * d1;
    #pragma unroll
    for (int off = 16; off; off >>= 1)
        s += __shfl_xor_sync(0xffffffffu, s, off);
    if (lane == 0) redf[wwid] = s;
    __syncthreads();
    if (tid == 0) {
        float t = 0.f;
        #pragma unroll
        for (int i = 0; i < FIN_THREADS / 32; i++) t += redf[i];
        if (out_size >= VQ_DIM + 1) out[VQ_DIM]     = (float)row;
        if (out_size >= VQ_DIM + 2) out[VQ_DIM + 1] = 0.25f * t / (float)VQ_DIM;
    }
}

extern "C" void kernel_launch(void* const* d_in, const int* in_sizes, int n_in,
                              void* d_out, int out_size) {
    const float* z = (const float*)d_in[0];
    const float* W = (const float*)d_in[1];
    if (n_in >= 2 && in_sizes[0] != VQ_DIM && in_sizes[1] == VQ_DIM) {
        z = (const float*)d_in[1];
        W = (const float*)d_in[0];
    }
    float* out = (float*)d_out;

    cudaLaunchConfig_t cfg1 = {};
    cfg1.gridDim  = dim3(ARG_BLOCKS);
    cfg1.blockDim = dim3(ARG_THREADS);
    cudaLaunchKernelEx(&cfg1, vq_argmax_kernel, z, W);

    cudaLaunchConfig_t cfg2 = {};
    cfg2.gridDim  = dim3(1);
    cfg2.blockDim = dim3(FIN_THREADS);
    cudaLaunchAttribute attr;
    attr.id = cudaLaunchAttributeProgrammaticStreamSerialization;
    attr.val.programmaticStreamSerializationAllowed = 1;
    cfg2.attrs = &attr;
    cfg2.numAttrs = 1;
    cudaLaunchKernelEx(&cfg2, vq_finalize_kernel, z, W, out, out_size);
}

// round 16
// speedup vs baseline: 1.0412x; 1.0400x over previous
#include <cuda_runtime.h>

// VectorQuantizer: argmax_k ( W[k] . z ), emit W[argmax], index, commit loss.
// W: 131072 x 1024 f32 (512 MiB) -> HBM wall ~7.4 TB/s (92% of 8 TB/s spec).
// Final probe: 444 blocks = 148 SMs x 3 CTAs, launch_bounds(256,3) -> 85-reg
// cap. Unique untested point where ptxas's NATURAL allocation (~77-81 regs,
// measured R2/R9) fits UNCAPPED while still giving 24 warps/SM (vs 16 at the
// free (256,2) point). Ledger: 4/SM 64-reg cap = 82.1 (best), 2/SM free =
// 82.7, 6/SM 42-reg cap = 84.5; fusion/work-stealing/spin-poll all banned.
// Rest byte-identical to the confirmed winner (8-deep __ldcs body, per-block
// slot stores, PDL finalize with z-prefetch).

#define VQ_DIM   1024
#define VQ_ROWS  131072
#define ARG_CTAS_PER_SM 3
#define ARG_BLOCKS  (148 * ARG_CTAS_PER_SM)   // 444: single persistent wave
#define ARG_THREADS 256
#define N_WARPS_TOT (ARG_BLOCKS * ARG_THREADS / 32)   // 3552 warps
#define FIN_THREADS 512

// Per-block packed (float_key(dot) << 32 | ~row). Overwritten every launch.
__device__ unsigned long long g_block_best[ARG_BLOCKS];

// Monotonic float -> uint key: preserves ordering for all finite floats.
__device__ __forceinline__ unsigned float_key(float f) {
    unsigned u = __float_as_uint(f);
    return (u & 0x80000000u) ? ~u : (u | 0x80000000u);
}

__global__ __launch_bounds__(ARG_THREADS, ARG_CTAS_PER_SM)  // 85-reg cap: free
void vq_argmax_kernel(const float* __restrict__ z, const float* __restrict__ W) {
    __shared__ float zs[VQ_DIM];
    __shared__ unsigned long long red64[ARG_THREADS / 32];

    const int tid  = threadIdx.x;
    const int lane = tid & 31;
    const int wwid = tid >> 5;

    // Stage z into shared (4 KB), vectorized.
    const float4* z4 = (const float4*)z;
    float4* zs4 = (float4*)zs;
    for (int i = tid; i < VQ_DIM / 4; i += ARG_THREADS)
        zs4[i] = z4[i];
    __syncthreads();

    // Let the finalize grid launch now: it prefetches z during our stream and
    // its griddepcontrol.wait releases the moment this grid retires.
    if (tid == 0)
        asm volatile("griddepcontrol.launch_dependents;");

    const int gwarp = (blockIdx.x * ARG_THREADS + tid) >> 5;

    unsigned long long best = 0ULL;

    for (int row = gwarp; row < VQ_ROWS; row += N_WARPS_TOT) {
        const float4* wr = (const float4*)(W + (size_t)row * VQ_DIM);
        // All 8 LDG.128s issued up front (max per-warp MLP), streaming hint.
        float4 w0 = __ldcs(wr + lane +   0);
        float4 w1 = __ldcs(wr + lane +  32);
        float4 w2 = __ldcs(wr + lane +  64);
        float4 w3 = __ldcs(wr + lane +  96);
        float4 w4 = __ldcs(wr + lane + 128);
        float4 w5 = __ldcs(wr + lane + 160);
        float4 w6 = __ldcs(wr + lane + 192);
        float4 w7 = __ldcs(wr + lane + 224);
        float a0, a1, a2, a3;
        { float4 p = zs4[lane +   0]; a0  = w0.x*p.x + w0.y*p.y + w0.z*p.z + w0.w*p.w; }
        { float4 p = zs4[lane +  32]; a1  = w1.x*p.x + w1.y*p.y + w1.z*p.z + w1.w*p.w; }
        { float4 p = zs4[lane +  64]; a2  = w2.x*p.x + w2.y*p.y + w2.z*p.z + w2.w*p.w; }
        { float4 p = zs4[lane +  96]; a3  = w3.x*p.x + w3.y*p.y + w3.z*p.z + w3.w*p.w; }
        { float4 p = zs4[lane + 128]; a0 += w4.x*p.x + w4.y*p.y + w4.z*p.z + w4.w*p.w; }
        { float4 p = zs4[lane + 160]; a1 += w5.x*p.x + w5.y*p.y + w5.z*p.z + w5.w*p.w; }
        { float4 p = zs4[lane + 192]; a2 += w6.x*p.x + w6.y*p.y + w6.z*p.z + w6.w*p.w; }
        { float4 p = zs4[lane + 224]; a3 += w7.x*p.x + w7.y*p.y + w7.z*p.z + w7.w*p.w; }
        float dot = (a0 + a1) + (a2 + a3);

        #pragma unroll
        for (int off = 16; off; off >>= 1)
            dot += __shfl_xor_sync(0xffffffffu, dot, off);

        // ~row in low bits: ties resolve to SMALLEST row (jnp.argmax semantics).
        unsigned long long p =
            ((unsigned long long)float_key(dot) << 32) |
            (unsigned long long)(0xFFFFFFFFu - (unsigned)row);
        if (p > best) best = p;
    }

    // One value per warp -> 8-entry smem max -> slot store (no atomics).
    if (lane == 0) red64[wwid] = best;
    __syncthreads();
    if (tid == 0) {
        unsigned long long v = red64[0];
        #pragma unroll
        for (int i = 1; i < ARG_THREADS / 32; i++)
            if (red64[i] > v) v = red64[i];
        g_block_best[blockIdx.x] = v;
    }
}

__global__ __launch_bounds__(FIN_THREADS)
void vq_finalize_kernel(const float* __restrict__ z,
                        const float* __restrict__ W,
                        float* __restrict__ out, int out_size) {
    __shared__ unsigned long long red64[FIN_THREADS / 32];
    __shared__ float redf[FIN_THREADS / 32];
    const int tid  = threadIdx.x;
    const int lane = tid & 31;
    const int wwid = tid >> 5;

    // Prefetch z (independent of the primary) BEFORE the PDL wait so the
    // DRAM latency overlaps the argmax stream/drain.
    float zv0 = z[tid];
    float zv1 = z[tid + FIN_THREADS];

    asm volatile("griddepcontrol.wait;" ::: "memory");

    // Scan the 444 slots (<=1 extra per thread, L2-hot).
    unsigned long long b = g_block_best[tid < ARG_BLOCKS ? tid : 0];
    if (tid + FIN_THREADS < ARG_BLOCKS) {
        unsigned long long v = g_block_best[tid + FIN_THREADS];
        if (v > b) b = v;
    }
    #pragma unroll
    for (int off = 16; off; off >>= 1) {
        unsigned long long o = __shfl_xor_sync(0xffffffffu, b, off);
        if (o > b) b = o;
    }
    if (lane == 0) red64[wwid] = b;
    __syncthreads();
    if (tid == 0) {
        unsigned long long v = red64[0];
        #pragma unroll
        for (int i = 1; i < FIN_THREADS / 32; i++)
            if (red64[i] > v) v = red64[i];
        red64[0] = v;
    }
    __syncthreads();
    const unsigned row = 0xFFFFFFFFu - (unsigned)(red64[0] & 0xFFFFFFFFull);
    const float* q = W + (size_t)row * VQ_DIM;

    // Copy winning row + commitment loss. 2 elems/thread.
    float q0 = q[tid];
    float q1 = q[tid + FIN_THREADS];
    if (tid < out_size) out[tid] = q0;
    if (tid + FIN_THREADS < out_size) out[tid + FIN_THREADS] = q1;
    float d0 = zv0 - q0, d1 = zv1 - q1;
    float s = d0 * d0 + d1 * d1;
    #pragma unroll
    for (int off = 16; off; off >>= 1)
        s += __shfl_xor_sync(0xffffffffu, s, off);
    if (lane == 0) redf[wwid] = s;
    __syncthreads();
    if (tid == 0) {
        float t = 0.f;
        #pragma unroll
        for (int i = 0; i < FIN_THREADS / 32; i++) t += redf[i];
        if (out_size >= VQ_DIM + 1) out[VQ_DIM]     = (float)row;
        if (out_size >= VQ_DIM + 2) out[VQ_DIM + 1] = 0.25f * t / (float)VQ_DIM;
    }
}

extern "C" void kernel_launch(void* const* d_in, const int* in_sizes, int n_in,
                              void* d_out, int out_size) {
    const float* z = (const float*)d_in[0];
    const float* W = (const float*)d_in[1];
    if (n_in >= 2 && in_sizes[0] != VQ_DIM && in_sizes[1] == VQ_DIM) {
        z = (const float*)d_in[1];
        W = (const float*)d_in[0];
    }
    float* out = (float*)d_out;

    cudaLaunchConfig_t cfg1 = {};
    cfg1.gridDim  = dim3(ARG_BLOCKS);
    cfg1.blockDim = dim3(ARG_THREADS);
    cudaLaunchKernelEx(&cfg1, vq_argmax_kernel, z, W);

    cudaLaunchConfig_t cfg2 = {};
    cfg2.gridDim  = dim3(1);
    cfg2.blockDim = dim3(FIN_THREADS);
    cudaLaunchAttribute attr;
    attr.id = cudaLaunchAttributeProgrammaticStreamSerialization;
    attr.val.programmaticStreamSerializationAllowed = 1;
    cfg2.attrs = &attr;
    cfg2.numAttrs = 1;
    cudaLaunchKernelEx(&cfg2, vq_finalize_kernel, z, W, out, out_size);
}

// round 17
// speedup vs baseline: 1.0458x; 1.0044x over previous
#include <cuda_runtime.h>

// VectorQuantizer: argmax_k ( W[k] . z ), emit W[argmax], index, commit loss.
// W: 131072 x 1024 f32 (512 MiB) -> HBM wall ~7.35 TB/s (92% of 8 TB/s spec).
// WINNER (80.74us, confirmation re-bench): 444 blocks = 148 SMs x 3 CTAs,
// launch_bounds(256,3) -> 85-reg cap, which leaves ptxas's NATURAL allocation
// (~77-81 regs) UNCAPPED while giving 24 warps/SM. Measured occupancy curve
// at 256 thr: 16w free=82.7, 24w free=80.7 (peak), 32w 64-cap=82.1,
// 48w 42-cap=84.5. Body: 8-deep front-batched LDG.128 (__ldcs), z in smem,
// packed (float_key << 32 | ~row) per-block slot stores; separate PDL
// finalize kernel with z-prefetch before griddepcontrol.wait.
// Banned by measurement: fused epilogue x3 (reg/occ collapse), 1 CTA/SM
// monolith (barrier coupling), spin-poll finalize, block-specialized
// finalizer, single-counter work stealing (LTS atomic serialization).

#define VQ_DIM   1024
#define VQ_ROWS  131072
#define ARG_CTAS_PER_SM 3
#define ARG_BLOCKS  (148 * ARG_CTAS_PER_SM)   // 444: single persistent wave
#define ARG_THREADS 256
#define N_WARPS_TOT (ARG_BLOCKS * ARG_THREADS / 32)   // 3552 warps
#define FIN_THREADS 512

// Per-block packed (float_key(dot) << 32 | ~row). Overwritten every launch.
__device__ unsigned long long g_block_best[ARG_BLOCKS];

// Monotonic float -> uint key: preserves ordering for all finite floats.
__device__ __forceinline__ unsigned float_key(float f) {
    unsigned u = __float_as_uint(f);
    return (u & 0x80000000u) ? ~u : (u | 0x80000000u);
}

__global__ __launch_bounds__(ARG_THREADS, ARG_CTAS_PER_SM)  // 85-reg cap: free
void vq_argmax_kernel(const float* __restrict__ z, const float* __restrict__ W) {
    __shared__ float zs[VQ_DIM];
    __shared__ unsigned long long red64[ARG_THREADS / 32];

    const int tid  = threadIdx.x;
    const int lane = tid & 31;
    const int wwid = tid >> 5;

    // Stage z into shared (4 KB), vectorized.
    const float4* z4 = (const float4*)z;
    float4* zs4 = (float4*)zs;
    for (int i = tid; i < VQ_DIM / 4; i += ARG_THREADS)
        zs4[i] = z4[i];
    __syncthreads();

    // Let the finalize grid launch now: it prefetches z during our stream and
    // its griddepcontrol.wait releases the moment this grid retires.
    if (tid == 0)
        asm volatile("griddepcontrol.launch_dependents;");

    const int gwarp = (blockIdx.x * ARG_THREADS + tid) >> 5;

    unsigned long long best = 0ULL;

    for (int row = gwarp; row < VQ_ROWS; row += N_WARPS_TOT) {
        const float4* wr = (const float4*)(W + (size_t)row * VQ_DIM);
        // All 8 LDG.128s issued up front (max per-warp MLP), streaming hint.
        float4 w0 = __ldcs(wr + lane +   0);
        float4 w1 = __ldcs(wr + lane +  32);
        float4 w2 = __ldcs(wr + lane +  64);
        float4 w3 = __ldcs(wr + lane +  96);
        float4 w4 = __ldcs(wr + lane + 128);
        float4 w5 = __ldcs(wr + lane + 160);
        float4 w6 = __ldcs(wr + lane + 192);
        float4 w7 = __ldcs(wr + lane + 224);
        float a0, a1, a2, a3;
        { float4 p = zs4[lane +   0]; a0  = w0.x*p.x + w0.y*p.y + w0.z*p.z + w0.w*p.w; }
        { float4 p = zs4[lane +  32]; a1  = w1.x*p.x + w1.y*p.y + w1.z*p.z + w1.w*p.w; }
        { float4 p = zs4[lane +  64]; a2  = w2.x*p.x + w2.y*p.y + w2.z*p.z + w2.w*p.w; }
        { float4 p = zs4[lane +  96]; a3  = w3.x*p.x + w3.y*p.y + w3.z*p.z + w3.w*p.w; }
        { float4 p = zs4[lane + 128]; a0 += w4.x*p.x + w4.y*p.y + w4.z*p.z + w4.w*p.w; }
        { float4 p = zs4[lane + 160]; a1 += w5.x*p.x + w5.y*p.y + w5.z*p.z + w5.w*p.w; }
        { float4 p = zs4[lane + 192]; a2 += w6.x*p.x + w6.y*p.y + w6.z*p.z + w6.w*p.w; }
        { float4 p = zs4[lane + 224]; a3 += w7.x*p.x + w7.y*p.y + w7.z*p.z + w7.w*p.w; }
        float dot = (a0 + a1) + (a2 + a3);

        #pragma unroll
        for (int off = 16; off; off >>= 1)
            dot += __shfl_xor_sync(0xffffffffu, dot, off);

        // ~row in low bits: ties resolve to SMALLEST row (jnp.argmax semantics).
        unsigned long long p =
            ((unsigned long long)float_key(dot) << 32) |
            (unsigned long long)(0xFFFFFFFFu - (unsigned)row);
        if (p > best) best = p;
    }

    // One value per warp -> 8-entry smem max -> slot store (no atomics).
    if (lane == 0) red64[wwid] = best;
    __syncthreads();
    if (tid == 0) {
        unsigned long long v = red64[0];
        #pragma unroll
        for (int i = 1; i < ARG_THREADS / 32; i++)
            if (red64[i] > v) v = red64[i];
        g_block_best[blockIdx.x] = v;
    }
}

__global__ __launch_bounds__(FIN_THREADS)
void vq_finalize_kernel(const float* __restrict__ z,
                        const float* __restrict__ W,
                        float* __restrict__ out, int out_size) {
    __shared__ unsigned long long red64[FIN_THREADS / 32];
    __shared__ float redf[FIN_THREADS / 32];
    const int tid  = threadIdx.x;
    const int lane = tid & 31;
    const int wwid = tid >> 5;

    // Prefetch z (independent of the primary) BEFORE the PDL wait so the
    // DRAM latency overlaps the argmax stream/drain.
    float zv0 = z[tid];
    float zv1 = z[tid + FIN_THREADS];

    asm volatile("griddepcontrol.wait;" ::: "memory");

    // Scan the 444 slots (<=1 extra per thread, L2-hot).
    unsigned long long b = g_block_best[tid < ARG_BLOCKS ? tid : 0];
    if (tid + FIN_THREADS < ARG_BLOCKS) {
        unsigned long long v = g_block_best[tid + FIN_THREADS];
        if (v > b) b = v;
    }
    #pragma unroll
    for (int off = 16; off; off >>= 1) {
        unsigned long long o = __shfl_xor_sync(0xffffffffu, b, off);
        if (o > b) b = o;
    }
    if (lane == 0) red64[wwid] = b;
    __syncthreads();
    if (tid == 0) {
        unsigned long long v = red64[0];
        #pragma unroll
        for (int i = 1; i < FIN_THREADS / 32; i++)
            if (red64[i] > v) v = red64[i];
        red64[0] = v;
    }
    __syncthreads();
    const unsigned row = 0xFFFFFFFFu - (unsigned)(red64[0] & 0xFFFFFFFFull);
    const float* q = W + (size_t)row * VQ_DIM;

    // Copy winning row + commitment loss. 2 elems/thread.
    float q0 = q[tid];
    float q1 = q[tid + FIN_THREADS];
    if (tid < out_size) out[tid] = q0;
    if (tid + FIN_THREADS < out_size) out[tid + FIN_THREADS] = q1;
    float d0 = zv0 - q0, d1 = zv1 - q1;
    float s = d0 * d0 + d1 * d1;
    #pragma unroll
    for (int off = 16; off; off >>= 1)
        s += __shfl_xor_sync(0xffffffffu, s, off);
    if (lane == 0) redf[wwid] = s;
    __syncthreads();
    if (tid == 0) {
        float t = 0.f;
        #pragma unroll
        for (int i = 0; i < FIN_THREADS / 32; i++) t += redf[i];
        if (out_size >= VQ_DIM + 1) out[VQ_DIM]     = (float)row;
        if (out_size >= VQ_DIM + 2) out[VQ_DIM + 1] = 0.25f * t / (float)VQ_DIM;
    }
}

extern "C" void kernel_launch(void* const* d_in, const int* in_sizes, int n_in,
                              void* d_out, int out_size) {
    const float* z = (const float*)d_in[0];
    const float* W = (const float*)d_in[1];
    if (n_in >= 2 && in_sizes[0] != VQ_DIM && in_sizes[1] == VQ_DIM) {
        z = (const float*)d_in[1];
        W = (const float*)d_in[0];
    }
    float* out = (float*)d_out;

    cudaLaunchConfig_t cfg1 = {};
    cfg1.gridDim  = dim3(ARG_BLOCKS);
    cfg1.blockDim = dim3(ARG_THREADS);
    cudaLaunchKernelEx(&cfg1, vq_argmax_kernel, z, W);

    cudaLaunchConfig_t cfg2 = {};
    cfg2.gridDim  = dim3(1);
    cfg2.blockDim = dim3(FIN_THREADS);
    cudaLaunchAttribute attr;
    attr.id = cudaLaunchAttributeProgrammaticStreamSerialization;
    attr.val.programmaticStreamSerializationAllowed = 1;
    cfg2.attrs = &attr;
    cfg2.numAttrs = 1;
    cudaLaunchKernelEx(&cfg2, vq_finalize_kernel, z, W, out, out_size);
}